// round 1
// baseline (speedup 1.0000x reference)
#include <cuda_runtime.h>
#include <cstdint>

#define NN 2048
#define KK 16
#define FF 256
#define OO 256

// ---------------- scratch (device globals; no allocation) ----------------
__device__ uint32_t g_mask[NN];          // membership bitmask per node
__device__ int      g_cnt[KK];           // cluster sizes
__device__ int      g_list[KK][NN];      // per-cluster node lists (deterministic order)
__device__ float    g_h[NN * OO];        // accumulated pre-relu node features
__device__ float    g_coarsen[KK * KK];  // coarsened adjacency
__device__ float    g_sum[OO];           // BN column sums
__device__ float    g_sumsq[OO];         // BN column sum of squares

// ---------------- kernel 1: partition + zero accumulators ----------------
__global__ __launch_bounds__(256) void k_partition(const float* __restrict__ x,
                                                   const float* __restrict__ wp,
                                                   const float* __restrict__ bp) {
    __shared__ float wsh[KK][FF];  // transposed weight [k][f]
    int tid = threadIdx.x;
    int b = blockIdx.x;

    // load w_part transposed into shared
    for (int e = tid; e < FF * KK; e += 256) {
        int f = e / KK, k = e % KK;
        wsh[k][f] = wp[e];
    }
    // zero g_h slice (256 blocks * 2048 = NN*OO)
    #pragma unroll
    for (int q = 0; q < 8; q++)
        g_h[b * 2048 + q * 256 + tid] = 0.f;
    if (b == 0) {
        if (tid < KK * KK) g_coarsen[tid] = 0.f;
        g_sum[tid] = 0.f;
        g_sumsq[tid] = 0.f;
    }
    __syncthreads();

    int w = tid >> 5, lane = tid & 31;
    int i = b * 8 + w;  // node id

    float acc[KK];
    #pragma unroll
    for (int k = 0; k < KK; k++) acc[k] = 0.f;

    #pragma unroll
    for (int it = 0; it < 8; it++) {
        int f = it * 32 + lane;
        float xv = x[i * FF + f];
        #pragma unroll
        for (int k = 0; k < KK; k++) acc[k] += xv * wsh[k][f];
    }
    #pragma unroll
    for (int k = 0; k < KK; k++) {
        #pragma unroll
        for (int off = 16; off > 0; off >>= 1)
            acc[k] += __shfl_xor_sync(0xffffffffu, acc[k], off);
    }
    // all lanes now hold the full 16 logits
    float mx = -1.f;
    #pragma unroll
    for (int k = 0; k < KK; k++) {
        float r = fmaxf(acc[k] + bp[k], 0.f);  // relu(logit)
        acc[k] = r;
        mx = fmaxf(mx, r);
    }
    uint32_t msk = 0;
    #pragma unroll
    for (int k = 0; k < KK; k++)
        if (acc[k] == mx) msk |= (1u << k);
    if (lane == 0) g_mask[i] = msk;
}

// ---------------- kernel 2: deterministic per-cluster lists ----------------
__global__ __launch_bounds__(512) void k_lists() {
    int w = threadIdx.x >> 5, lane = threadIdx.x & 31;
    if (w >= KK) return;
    int cnt = 0;
    #pragma unroll 4
    for (int base = 0; base < NN; base += 32) {
        uint32_t m = g_mask[base + lane];
        int pred = (m >> w) & 1u;
        unsigned bal = __ballot_sync(0xffffffffu, pred);
        if (pred) {
            int pos = cnt + __popc(bal & ((1u << lane) - 1u));
            g_list[w][pos] = base + lane;
        }
        cnt += __popc(bal);
    }
    if (lane == 0) g_cnt[w] = cnt;
}

// ---------------- kernel 3: coarsen_adj = M adj M^T ----------------
__global__ __launch_bounds__(256) void k_coarsen(const float* __restrict__ adj) {
    __shared__ uint32_t msh[NN];
    int tid = threadIdx.x;
    for (int e = tid; e < NN; e += 256) msh[e] = g_mask[e];
    __syncthreads();

    int w = tid >> 5, lane = tid & 31;
    for (int i = blockIdx.x * 8 + w; i < NN; i += 512) {
        float acc[KK];
        #pragma unroll
        for (int k = 0; k < KK; k++) acc[k] = 0.f;
        const float* row = adj + (size_t)i * NN;
        #pragma unroll 4
        for (int jt = 0; jt < NN / 32; jt++) {
            int j = jt * 32 + lane;
            float v = row[j];
            uint32_t mj = msh[j];
            #pragma unroll
            for (int bb = 0; bb < KK; bb++)
                if (mj & (1u << bb)) acc[bb] += v;
        }
        uint32_t mi = g_mask[i];
        #pragma unroll
        for (int bb = 0; bb < KK; bb++) {
            float val = acc[bb];
            #pragma unroll
            for (int off = 16; off > 0; off >>= 1)
                val += __shfl_xor_sync(0xffffffffu, val, off);
            if (lane == 0) {
                uint32_t ma = mi;
                while (ma) {
                    int a = __ffs(ma) - 1;
                    ma &= ma - 1;
                    atomicAdd(&g_coarsen[a * KK + bb], val);
                }
            }
        }
    }
}

// ---------------- kernel 4: fused per-cluster GCN ----------------
// grid (128 tiles, 16 clusters), 256 threads; row tile = 16 nodes of cluster k.
// stage1: t[r,f] = sum_{j in cluster} adj[gi_r, gj]*x[gj,f] + 2*x[gi_r,f]
// stage2: u = t @ W_k;  L2-normalize rows;  atomicAdd into g_h
__global__ __launch_bounds__(256) void k_gcn(const float* __restrict__ adj,
                                             const float* __restrict__ x,
                                             const float* __restrict__ W) {
    int k = blockIdx.y;
    int tile = blockIdx.x;
    int cnt = g_cnt[k];
    if (tile * 16 >= cnt) return;

    __shared__ float t_sh[16][FF];    // 16 KB
    __shared__ float xw_sh[16][FF];   // 16 KB (x chunk, then W chunk)
    __shared__ float a_sh[16][16];    // 1 KB
    __shared__ int   gi_sh[16];

    int tid = threadIdx.x;
    int w = tid >> 5, lane = tid & 31;

    if (tid < 16) {
        int pos = tile * 16 + tid;
        gi_sh[tid] = (pos < cnt) ? g_list[k][pos] : -1;
    }
    __syncthreads();

    int r0 = 2 * w, r1 = 2 * w + 1;
    int gi0 = gi_sh[r0], gi1 = gi_sh[r1];

    // accumulators for columns {lane*4..+3} and {128+lane*4..+3}
    float acc0[8], acc1[8];
    #pragma unroll
    for (int c = 0; c < 8; c++) { acc0[c] = 0.f; acc1[c] = 0.f; }

    // -------- stage 1: t-tile --------
    for (int jb = 0; jb < cnt; jb += 16) {
        __syncthreads();  // protect xw_sh reuse from previous inner loop
        {   // adj sub-block gather: 16x16
            int r = tid >> 4, jj = tid & 15;
            int posj = jb + jj;
            int gj = (posj < cnt) ? g_list[k][posj] : g_list[k][0];
            int gi = gi_sh[r];
            float a = 0.f;
            if (gi >= 0 && posj < cnt) a = adj[(size_t)gi * NN + gj];
            a_sh[r][jj] = a;
        }
        {   // x rows gather: 16 x 256 (coalesced float4)
            int jr = tid >> 4, tl = tid & 15;
            int posj = jb + jr;
            int gj = (posj < cnt) ? g_list[k][posj] : g_list[k][0];
            const float4* src = reinterpret_cast<const float4*>(x + (size_t)gj * FF);
            float4* dst = reinterpret_cast<float4*>(&xw_sh[jr][0]);
            #pragma unroll
            for (int it = 0; it < 4; it++) dst[tl + it * 16] = src[tl + it * 16];
        }
        __syncthreads();
        #pragma unroll
        for (int jj = 0; jj < 16; jj++) {
            float a0 = a_sh[r0][jj], a1 = a_sh[r1][jj];
            float4 xv0 = *reinterpret_cast<const float4*>(&xw_sh[jj][lane * 4]);
            float4 xv1 = *reinterpret_cast<const float4*>(&xw_sh[jj][128 + lane * 4]);
            acc0[0] += a0 * xv0.x; acc0[1] += a0 * xv0.y;
            acc0[2] += a0 * xv0.z; acc0[3] += a0 * xv0.w;
            acc0[4] += a0 * xv1.x; acc0[5] += a0 * xv1.y;
            acc0[6] += a0 * xv1.z; acc0[7] += a0 * xv1.w;
            acc1[0] += a1 * xv0.x; acc1[1] += a1 * xv0.y;
            acc1[2] += a1 * xv0.z; acc1[3] += a1 * xv0.w;
            acc1[4] += a1 * xv1.x; acc1[5] += a1 * xv1.y;
            acc1[6] += a1 * xv1.z; acc1[7] += a1 * xv1.w;
        }
    }
    // + 2*x[i]
    if (gi0 >= 0) {
        float4 xa = *reinterpret_cast<const float4*>(x + (size_t)gi0 * FF + lane * 4);
        float4 xb = *reinterpret_cast<const float4*>(x + (size_t)gi0 * FF + 128 + lane * 4);
        acc0[0] += 2.f * xa.x; acc0[1] += 2.f * xa.y; acc0[2] += 2.f * xa.z; acc0[3] += 2.f * xa.w;
        acc0[4] += 2.f * xb.x; acc0[5] += 2.f * xb.y; acc0[6] += 2.f * xb.z; acc0[7] += 2.f * xb.w;
    }
    if (gi1 >= 0) {
        float4 xa = *reinterpret_cast<const float4*>(x + (size_t)gi1 * FF + lane * 4);
        float4 xb = *reinterpret_cast<const float4*>(x + (size_t)gi1 * FF + 128 + lane * 4);
        acc1[0] += 2.f * xa.x; acc1[1] += 2.f * xa.y; acc1[2] += 2.f * xa.z; acc1[3] += 2.f * xa.w;
        acc1[4] += 2.f * xb.x; acc1[5] += 2.f * xb.y; acc1[6] += 2.f * xb.z; acc1[7] += 2.f * xb.w;
    }
    __syncthreads();  // make sure everyone done reading xw_sh before t_sh fill races? (t_sh untouched; safe)
    *reinterpret_cast<float4*>(&t_sh[r0][lane * 4])       = make_float4(acc0[0], acc0[1], acc0[2], acc0[3]);
    *reinterpret_cast<float4*>(&t_sh[r0][128 + lane * 4]) = make_float4(acc0[4], acc0[5], acc0[6], acc0[7]);
    *reinterpret_cast<float4*>(&t_sh[r1][lane * 4])       = make_float4(acc1[0], acc1[1], acc1[2], acc1[3]);
    *reinterpret_cast<float4*>(&t_sh[r1][128 + lane * 4]) = make_float4(acc1[4], acc1[5], acc1[6], acc1[7]);

    // -------- stage 2: u = t @ W_k --------
    #pragma unroll
    for (int c = 0; c < 8; c++) { acc0[c] = 0.f; acc1[c] = 0.f; }
    const float* Wk = W + (size_t)k * FF * OO;
    for (int fb = 0; fb < FF; fb += 16) {
        __syncthreads();
        {   // load W chunk [16][256]
            int fr = tid >> 4, tl = tid & 15;
            const float4* src = reinterpret_cast<const float4*>(Wk + (size_t)(fb + fr) * OO);
            float4* dst = reinterpret_cast<float4*>(&xw_sh[fr][0]);
            #pragma unroll
            for (int it = 0; it < 4; it++) dst[tl + it * 16] = src[tl + it * 16];
        }
        __syncthreads();
        #pragma unroll
        for (int ff = 0; ff < 16; ff++) {
            float t0 = t_sh[r0][fb + ff], t1 = t_sh[r1][fb + ff];
            float4 wv0 = *reinterpret_cast<const float4*>(&xw_sh[ff][lane * 4]);
            float4 wv1 = *reinterpret_cast<const float4*>(&xw_sh[ff][128 + lane * 4]);
            acc0[0] += t0 * wv0.x; acc0[1] += t0 * wv0.y;
            acc0[2] += t0 * wv0.z; acc0[3] += t0 * wv0.w;
            acc0[4] += t0 * wv1.x; acc0[5] += t0 * wv1.y;
            acc0[6] += t0 * wv1.z; acc0[7] += t0 * wv1.w;
            acc1[0] += t1 * wv0.x; acc1[1] += t1 * wv0.y;
            acc1[2] += t1 * wv0.z; acc1[3] += t1 * wv0.w;
            acc1[4] += t1 * wv1.x; acc1[5] += t1 * wv1.y;
            acc1[6] += t1 * wv1.z; acc1[7] += t1 * wv1.w;
        }
    }

    // -------- L2 normalize rows + scatter --------
    if (gi0 >= 0) {
        float ss = 0.f;
        #pragma unroll
        for (int c = 0; c < 8; c++) ss += acc0[c] * acc0[c];
        #pragma unroll
        for (int off = 16; off > 0; off >>= 1)
            ss += __shfl_xor_sync(0xffffffffu, ss, off);
        float rn = 1.f / fmaxf(sqrtf(ss), 1e-12f);
        #pragma unroll
        for (int c = 0; c < 4; c++)
            atomicAdd(&g_h[(size_t)gi0 * OO + lane * 4 + c], acc0[c] * rn);
        #pragma unroll
        for (int c = 4; c < 8; c++)
            atomicAdd(&g_h[(size_t)gi0 * OO + 128 + lane * 4 + (c - 4)], acc0[c] * rn);
    }
    if (gi1 >= 0) {
        float ss = 0.f;
        #pragma unroll
        for (int c = 0; c < 8; c++) ss += acc1[c] * acc1[c];
        #pragma unroll
        for (int off = 16; off > 0; off >>= 1)
            ss += __shfl_xor_sync(0xffffffffu, ss, off);
        float rn = 1.f / fmaxf(sqrtf(ss), 1e-12f);
        #pragma unroll
        for (int c = 0; c < 4; c++)
            atomicAdd(&g_h[(size_t)gi1 * OO + lane * 4 + c], acc1[c] * rn);
        #pragma unroll
        for (int c = 4; c < 8; c++)
            atomicAdd(&g_h[(size_t)gi1 * OO + 128 + lane * 4 + (c - 4)], acc1[c] * rn);
    }
}

// ---------------- kernel 5: BN column stats over relu(h) ----------------
__global__ __launch_bounds__(256) void k_stats() {
    int o = threadIdx.x;
    int rb = blockIdx.x * 32;
    float s = 0.f, ss = 0.f;
    #pragma unroll 8
    for (int r = 0; r < 32; r++) {
        float v = fmaxf(g_h[(size_t)(rb + r) * OO + o], 0.f);
        s += v;
        ss += v * v;
    }
    atomicAdd(&g_sum[o], s);
    atomicAdd(&g_sumsq[o], ss);
}

// ---------------- kernel 6: final output ----------------
__global__ __launch_bounds__(256) void k_final(float* __restrict__ out) {
    int k = blockIdx.x, o = threadIdx.x;
    int cnt = g_cnt[k];
    float S = 0.f;
    for (int p = 0; p < cnt; p++) {
        int gi = g_list[k][p];
        S += fmaxf(g_h[(size_t)gi * OO + o], 0.f);
    }
    float mean = g_sum[o] * (1.f / NN);
    float var = g_sumsq[o] * (1.f / NN) - mean * mean;
    float rstd = rsqrtf(var + 1e-5f);
    out[k * OO + o] = (S - (float)cnt * mean) * rstd;
    if (o < KK) out[KK * OO + k * KK + o] = g_coarsen[k * KK + o];
}

// ---------------- launch ----------------
extern "C" void kernel_launch(void* const* d_in, const int* in_sizes, int n_in,
                              void* d_out, int out_size) {
    const float* x   = (const float*)d_in[0];
    const float* adj = (const float*)d_in[1];
    const float* wp  = (const float*)d_in[2];
    const float* bp  = (const float*)d_in[3];
    const float* W   = (const float*)d_in[4];
    float* out = (float*)d_out;

    k_partition<<<256, 256>>>(x, wp, bp);
    k_lists<<<1, 512>>>();
    k_coarsen<<<64, 256>>>(adj);
    k_gcn<<<dim3(128, 16), 256>>>(adj, x, W);
    k_stats<<<64, 256>>>();
    k_final<<<KK, 256>>>(out);
}

// round 2
// speedup vs baseline: 1.0777x; 1.0777x over previous
#include <cuda_runtime.h>
#include <cstdint>

#define NN 2048
#define KK 16
#define FF 256
#define OO 256

// ---------------- scratch (device globals; no allocation) ----------------
__device__ uint32_t g_mask[NN];            // membership bitmask per node
__device__ int      g_cnt[KK];             // cluster sizes
__device__ int      g_list[KK][NN];        // per-cluster node lists
__device__ float    g_t[KK * NN * FF / 16 * 16];  // cluster-sorted t rows: [(k*NN+pos)*FF]
__device__ float    g_y[KK * NN * OO / 16 * 16];  // cluster-sorted y rows
__device__ float    g_h[NN * OO];          // accumulated node features (pre-relu)
__device__ float    g_coarsen[KK * KK];
__device__ float    g_sum[OO];
__device__ float    g_sumsq[OO];

// ---------------- kernel 1: partition + zero accumulators ----------------
__global__ __launch_bounds__(256) void k_partition(const float* __restrict__ x,
                                                   const float* __restrict__ wp,
                                                   const float* __restrict__ bp) {
    __shared__ float wsh[KK][FF];
    int tid = threadIdx.x;
    int b = blockIdx.x;

    for (int e = tid; e < FF * KK; e += 256) {
        int f = e / KK, k = e % KK;
        wsh[k][f] = wp[e];
    }
    #pragma unroll
    for (int q = 0; q < 8; q++)
        g_h[b * 2048 + q * 256 + tid] = 0.f;
    if (b == 0) {
        if (tid < KK * KK) g_coarsen[tid] = 0.f;
        g_sum[tid] = 0.f;
        g_sumsq[tid] = 0.f;
    }
    __syncthreads();

    int w = tid >> 5, lane = tid & 31;
    int i = b * 8 + w;

    float acc[KK];
    #pragma unroll
    for (int k = 0; k < KK; k++) acc[k] = 0.f;

    #pragma unroll
    for (int it = 0; it < 8; it++) {
        int f = it * 32 + lane;
        float xv = x[i * FF + f];
        #pragma unroll
        for (int k = 0; k < KK; k++) acc[k] += xv * wsh[k][f];
    }
    #pragma unroll
    for (int k = 0; k < KK; k++) {
        #pragma unroll
        for (int off = 16; off > 0; off >>= 1)
            acc[k] += __shfl_xor_sync(0xffffffffu, acc[k], off);
    }
    float mx = -1.f;
    #pragma unroll
    for (int k = 0; k < KK; k++) {
        float r = fmaxf(acc[k] + bp[k], 0.f);
        acc[k] = r;
        mx = fmaxf(mx, r);
    }
    uint32_t msk = 0;
    #pragma unroll
    for (int k = 0; k < KK; k++)
        if (acc[k] == mx) msk |= (1u << k);
    if (lane == 0) g_mask[i] = msk;
}

// ---------------- kernel 2: deterministic per-cluster lists ----------------
__global__ __launch_bounds__(512) void k_lists() {
    int w = threadIdx.x >> 5, lane = threadIdx.x & 31;
    int cnt = 0;
    #pragma unroll 4
    for (int base = 0; base < NN; base += 32) {
        uint32_t m = g_mask[base + lane];
        int pred = (m >> w) & 1u;
        unsigned bal = __ballot_sync(0xffffffffu, pred);
        if (pred) {
            int pos = cnt + __popc(bal & ((1u << lane) - 1u));
            g_list[w][pos] = base + lane;
        }
        cnt += __popc(bal);
    }
    if (lane == 0) g_cnt[w] = cnt;
}

// ---------------- kernel 3: coarsen_adj = M adj M^T ----------------
// 256 blocks x 8 warps: one adj row per warp, float4 loads.
__global__ __launch_bounds__(256) void k_coarsen(const float* __restrict__ adj) {
    __shared__ uint32_t msh[NN];
    int tid = threadIdx.x;
    for (int e = tid; e < NN; e += 256) msh[e] = g_mask[e];
    __syncthreads();

    int w = tid >> 5, lane = tid & 31;
    int i = blockIdx.x * 8 + w;

    float acc[KK];
    #pragma unroll
    for (int k = 0; k < KK; k++) acc[k] = 0.f;
    const float4* row = reinterpret_cast<const float4*>(adj + (size_t)i * NN);
    #pragma unroll 2
    for (int jt = 0; jt < NN / 128; jt++) {
        int j4 = jt * 32 + lane;       // float4 index
        float4 v = row[j4];
        int j = j4 * 4;
        uint32_t m0 = msh[j], m1 = msh[j + 1], m2 = msh[j + 2], m3 = msh[j + 3];
        #pragma unroll
        for (int bb = 0; bb < KK; bb++) {
            float s = 0.f;
            if (m0 & (1u << bb)) s += v.x;
            if (m1 & (1u << bb)) s += v.y;
            if (m2 & (1u << bb)) s += v.z;
            if (m3 & (1u << bb)) s += v.w;
            acc[bb] += s;
        }
    }
    uint32_t mi = g_mask[i];
    #pragma unroll
    for (int bb = 0; bb < KK; bb++) {
        float val = acc[bb];
        #pragma unroll
        for (int off = 16; off > 0; off >>= 1)
            val += __shfl_xor_sync(0xffffffffu, val, off);
        if (lane == 0) {
            uint32_t ma = mi;
            while (ma) {
                int a = __ffs(ma) - 1;
                ma &= ma - 1;
                atomicAdd(&g_coarsen[a * KK + bb], val);
            }
        }
    }
}

// ---------------- kernel 4: aggregation t = A_kk X_k + 2 X_k ----------------
// grid (128 tiles, KK, 2 halves), 256 threads. Tile: 16 rows x 128 features.
__global__ __launch_bounds__(256) void k_agg(const float* __restrict__ adj,
                                             const float* __restrict__ x) {
    int k = blockIdx.y;
    int tile = blockIdx.x;
    int half = blockIdx.z;
    int cnt = g_cnt[k];
    if (tile * 16 >= cnt) return;

    __shared__ float a_sh[16][16];
    __shared__ float x_sh[16][128];
    __shared__ int   gi_sh[16];

    int tid = threadIdx.x;
    if (tid < 16) {
        int pos = tile * 16 + tid;
        gi_sh[tid] = (pos < cnt) ? g_list[k][pos] : -1;
    }
    __syncthreads();

    int r = tid >> 4, c16 = tid & 15;  // r: row 0..15, c16: feature group
    int gi = gi_sh[r];
    int fbase = half * 128 + c16 * 8;

    float acc[8];
    #pragma unroll
    for (int q = 0; q < 8; q++) acc[q] = 0.f;

    for (int jb = 0; jb < cnt; jb += 16) {
        __syncthreads();
        // adj sub-block 16x16 (thread (r,c16) loads one element)
        {
            int posj = jb + c16;
            int gj = (posj < cnt) ? g_list[k][posj] : 0;
            float a = 0.f;
            if (gi >= 0 && posj < cnt) a = adj[(size_t)gi * NN + gj];
            a_sh[r][c16] = a;
        }
        // x rows 16 x 128 (this half), coalesced
        {
            int jr = tid >> 4;           // row of chunk
            int posj = jb + jr;
            int gj = (posj < cnt) ? g_list[k][posj] : g_list[k][0];
            const float4* src = reinterpret_cast<const float4*>(x + (size_t)gj * FF + half * 128);
            float4* dst = reinterpret_cast<float4*>(&x_sh[jr][0]);
            dst[c16] = src[c16];
            dst[c16 + 16] = src[c16 + 16];
        }
        __syncthreads();
        #pragma unroll
        for (int jj = 0; jj < 16; jj++) {
            float a = a_sh[r][jj];
            float4 v0 = *reinterpret_cast<const float4*>(&x_sh[jj][c16 * 8]);
            float4 v1 = *reinterpret_cast<const float4*>(&x_sh[jj][c16 * 8 + 4]);
            acc[0] += a * v0.x; acc[1] += a * v0.y; acc[2] += a * v0.z; acc[3] += a * v0.w;
            acc[4] += a * v1.x; acc[5] += a * v1.y; acc[6] += a * v1.z; acc[7] += a * v1.w;
        }
    }

    if (gi >= 0) {
        const float4* xr = reinterpret_cast<const float4*>(x + (size_t)gi * FF + fbase);
        float4 xa = xr[0], xb = xr[1];
        acc[0] += 2.f * xa.x; acc[1] += 2.f * xa.y; acc[2] += 2.f * xa.z; acc[3] += 2.f * xa.w;
        acc[4] += 2.f * xb.x; acc[5] += 2.f * xb.y; acc[6] += 2.f * xb.z; acc[7] += 2.f * xb.w;
        float* dst = g_t + (size_t)(k * NN + tile * 16 + r) * FF + fbase;
        *reinterpret_cast<float4*>(dst)     = make_float4(acc[0], acc[1], acc[2], acc[3]);
        *reinterpret_cast<float4*>(dst + 4) = make_float4(acc[4], acc[5], acc[6], acc[7]);
    }
}

// ---------------- kernel 5: y = t @ W_k (per-cluster GEMM) ----------------
// grid (32 row-tiles, KK, 4 col-tiles), 256 threads, 64x64 tile, 4x4 per thread.
__global__ __launch_bounds__(256) void k_gemm(const float* __restrict__ W) {
    int tile_r = blockIdx.x;
    int k = blockIdx.y;
    int ct = blockIdx.z;
    int cnt = g_cnt[k];
    if (tile_r * 64 >= cnt) return;

    __shared__ float t_sh[64][16];
    __shared__ float w_sh[16][64];

    int tid = threadIdx.x;
    int tx = tid & 15, ty = tid >> 4;
    int row0 = tile_r * 64, col0 = ct * 64;
    const float* tb = g_t + (size_t)(k * NN + row0) * FF;
    const float* Wk = W + (size_t)k * FF * OO;

    float acc[4][4];
    #pragma unroll
    for (int i = 0; i < 4; i++)
        #pragma unroll
        for (int j = 0; j < 4; j++) acc[i][j] = 0.f;

    int rr = tid >> 2, q = (tid & 3) * 4;    // t load mapping
    int fr = tid >> 4, cc = (tid & 15) * 4;  // w load mapping

    for (int kb = 0; kb < FF; kb += 16) {
        __syncthreads();
        *reinterpret_cast<float4*>(&t_sh[rr][q]) =
            *reinterpret_cast<const float4*>(tb + (size_t)rr * FF + kb + q);
        *reinterpret_cast<float4*>(&w_sh[fr][cc]) =
            *reinterpret_cast<const float4*>(Wk + (size_t)(kb + fr) * OO + col0 + cc);
        __syncthreads();
        #pragma unroll
        for (int kk = 0; kk < 16; kk++) {
            float tv0 = t_sh[ty * 4 + 0][kk];
            float tv1 = t_sh[ty * 4 + 1][kk];
            float tv2 = t_sh[ty * 4 + 2][kk];
            float tv3 = t_sh[ty * 4 + 3][kk];
            float4 wv = *reinterpret_cast<const float4*>(&w_sh[kk][tx * 4]);
            acc[0][0] += tv0 * wv.x; acc[0][1] += tv0 * wv.y; acc[0][2] += tv0 * wv.z; acc[0][3] += tv0 * wv.w;
            acc[1][0] += tv1 * wv.x; acc[1][1] += tv1 * wv.y; acc[1][2] += tv1 * wv.z; acc[1][3] += tv1 * wv.w;
            acc[2][0] += tv2 * wv.x; acc[2][1] += tv2 * wv.y; acc[2][2] += tv2 * wv.z; acc[2][3] += tv2 * wv.w;
            acc[3][0] += tv3 * wv.x; acc[3][1] += tv3 * wv.y; acc[3][2] += tv3 * wv.z; acc[3][3] += tv3 * wv.w;
        }
    }

    #pragma unroll
    for (int i = 0; i < 4; i++) {
        float* dst = g_y + (size_t)(k * NN + row0 + ty * 4 + i) * OO + col0 + tx * 4;
        *reinterpret_cast<float4*>(dst) = make_float4(acc[i][0], acc[i][1], acc[i][2], acc[i][3]);
    }
}

// ---------------- kernel 6: L2 normalize rows + scatter into g_h ----------------
// warp per cluster row. grid (256, KK), 256 threads.
__global__ __launch_bounds__(256) void k_norm() {
    int k = blockIdx.y;
    int cnt = g_cnt[k];
    int w = threadIdx.x >> 5, lane = threadIdx.x & 31;
    int pos = blockIdx.x * 8 + w;
    if (pos >= cnt) return;
    int gi = g_list[k][pos];

    const float4* yr = reinterpret_cast<const float4*>(g_y + (size_t)(k * NN + pos) * OO);
    float4 a = yr[lane * 2], b = yr[lane * 2 + 1];
    float ss = a.x * a.x + a.y * a.y + a.z * a.z + a.w * a.w
             + b.x * b.x + b.y * b.y + b.z * b.z + b.w * b.w;
    #pragma unroll
    for (int off = 16; off > 0; off >>= 1)
        ss += __shfl_xor_sync(0xffffffffu, ss, off);
    float rn = 1.f / fmaxf(sqrtf(ss), 1e-12f);

    float* hb = g_h + (size_t)gi * OO + lane * 8;
    atomicAdd(hb + 0, a.x * rn); atomicAdd(hb + 1, a.y * rn);
    atomicAdd(hb + 2, a.z * rn); atomicAdd(hb + 3, a.w * rn);
    atomicAdd(hb + 4, b.x * rn); atomicAdd(hb + 5, b.y * rn);
    atomicAdd(hb + 6, b.z * rn); atomicAdd(hb + 7, b.w * rn);
}

// ---------------- kernel 7: BN column stats over relu(h) ----------------
__global__ __launch_bounds__(256) void k_stats() {
    int o = threadIdx.x;
    int rb = blockIdx.x * 32;
    float s = 0.f, ss = 0.f;
    #pragma unroll 8
    for (int r = 0; r < 32; r++) {
        float v = fmaxf(g_h[(size_t)(rb + r) * OO + o], 0.f);
        s += v;
        ss += v * v;
    }
    atomicAdd(&g_sum[o], s);
    atomicAdd(&g_sumsq[o], ss);
}

// ---------------- kernel 8: final output ----------------
__global__ __launch_bounds__(256) void k_final(float* __restrict__ out) {
    int k = blockIdx.x, o = threadIdx.x;
    int cnt = g_cnt[k];
    float S = 0.f;
    for (int p = 0; p < cnt; p++) {
        int gi = g_list[k][p];
        S += fmaxf(g_h[(size_t)gi * OO + o], 0.f);
    }
    float mean = g_sum[o] * (1.f / NN);
    float var = g_sumsq[o] * (1.f / NN) - mean * mean;
    float rstd = rsqrtf(var + 1e-5f);
    out[k * OO + o] = (S - (float)cnt * mean) * rstd;
    if (o < KK) out[KK * OO + k * KK + o] = g_coarsen[k * KK + o];
}

// ---------------- launch ----------------
extern "C" void kernel_launch(void* const* d_in, const int* in_sizes, int n_in,
                              void* d_out, int out_size) {
    const float* x   = (const float*)d_in[0];
    const float* adj = (const float*)d_in[1];
    const float* wp  = (const float*)d_in[2];
    const float* bp  = (const float*)d_in[3];
    const float* W   = (const float*)d_in[4];
    float* out = (float*)d_out;

    k_partition<<<256, 256>>>(x, wp, bp);
    k_lists<<<1, 512>>>();
    k_coarsen<<<256, 256>>>(adj);
    k_agg<<<dim3(128, KK, 2), 256>>>(adj, x);
    k_gemm<<<dim3(32, KK, 4), 256>>>(W);
    k_norm<<<dim3(256, KK), 256>>>();
    k_stats<<<64, 256>>>();
    k_final<<<KK, 256>>>(out);
}

// round 4
// speedup vs baseline: 1.3987x; 1.2979x over previous
#include <cuda_runtime.h>
#include <cstdint>

#define NN 2048
#define KK 16
#define FF 256
#define OO 256
#define ROWS_MAX 4096
#define TILES_MAX 64

// ---------------- scratch (device globals; no allocation) ----------------
__device__ uint32_t g_mask[NN];
__device__ int      g_cnt[KK];
__device__ int      g_off[KK];
__device__ int      g_list[KK][NN];
__device__ int      g_tilek[TILES_MAX];
__device__ int      g_rownode[ROWS_MAX];
__device__ float    g_xk[ROWS_MAX * FF];          // cluster-sorted x (zero padded)
__device__ float    g_ak[(size_t)ROWS_MAX * NN];  // cluster-sorted A_kk rows (zero padded)
__device__ float    g_t[ROWS_MAX * FF];
__device__ float    g_y[ROWS_MAX * OO];
__device__ float    g_h[NN * OO];
__device__ float    g_coarsen[KK * KK];
__device__ float    g_sum[OO];
__device__ float    g_sumsq[OO];

// ---------------- kernel 1: partition + zero accumulators ----------------
__global__ __launch_bounds__(256) void k_partition(const float* __restrict__ x,
                                                   const float* __restrict__ wp,
                                                   const float* __restrict__ bp) {
    __shared__ float wsh[KK][FF];
    int tid = threadIdx.x;
    int b = blockIdx.x;

    for (int e = tid; e < FF * KK; e += 256) {
        int f = e / KK, k = e % KK;
        wsh[k][f] = wp[e];
    }
    #pragma unroll
    for (int q = 0; q < 8; q++)
        g_h[b * 2048 + q * 256 + tid] = 0.f;
    if (b == 0) {
        if (tid < KK * KK) g_coarsen[tid] = 0.f;
        g_sum[tid] = 0.f;
        g_sumsq[tid] = 0.f;
    }
    __syncthreads();

    int w = tid >> 5, lane = tid & 31;
    int i = b * 8 + w;

    float acc[KK];
    #pragma unroll
    for (int k = 0; k < KK; k++) acc[k] = 0.f;

    #pragma unroll
    for (int it = 0; it < 8; it++) {
        int f = it * 32 + lane;
        float xv = x[i * FF + f];
        #pragma unroll
        for (int k = 0; k < KK; k++) acc[k] += xv * wsh[k][f];
    }
    #pragma unroll
    for (int k = 0; k < KK; k++) {
        #pragma unroll
        for (int off = 16; off > 0; off >>= 1)
            acc[k] += __shfl_xor_sync(0xffffffffu, acc[k], off);
    }
    float mx = -1.f;
    #pragma unroll
    for (int k = 0; k < KK; k++) {
        float r = fmaxf(acc[k] + bp[k], 0.f);
        acc[k] = r;
        mx = fmaxf(mx, r);
    }
    uint32_t msk = 0;
    #pragma unroll
    for (int k = 0; k < KK; k++)
        if (acc[k] == mx) msk |= (1u << k);
    if (lane == 0) g_mask[i] = msk;
}

// ---------------- kernel 2: lists + offsets + tile map + rownode ----------------
__global__ __launch_bounds__(512) void k_lists() {
    int tid = threadIdx.x;
    int w = tid >> 5, lane = tid & 31;
    __shared__ int scnt[KK];
    __shared__ int soff[KK + 1];

    if (w < KK) {
        int cnt = 0;
        for (int base = 0; base < NN; base += 32) {
            uint32_t m = g_mask[base + lane];
            int pred = (m >> w) & 1u;
            unsigned bal = __ballot_sync(0xffffffffu, pred);
            if (pred) {
                int pos = cnt + __popc(bal & ((1u << lane) - 1u));
                g_list[w][pos] = base + lane;
            }
            cnt += __popc(bal);
        }
        if (lane == 0) { g_cnt[w] = cnt; scnt[w] = cnt; }
    }
    __syncthreads();

    if (tid == 0) {
        int o = 0;
        for (int k = 0; k < KK; k++) {
            soff[k] = o;
            g_off[k] = o;
            o += (scnt[k] + 63) & ~63;
        }
        soff[KK] = o;
        for (int t = 0; t < TILES_MAX; t++) g_tilek[t] = -1;
        for (int k = 0; k < KK; k++) {
            int t0 = soff[k] >> 6;
            int t1 = (soff[k] + ((scnt[k] + 63) & ~63)) >> 6;
            for (int t = t0; t < t1; t++) g_tilek[t] = k;
        }
    }
    __syncthreads();

    for (int r = tid; r < ROWS_MAX; r += 512) g_rownode[r] = -1;
    __syncthreads();
    for (int k = 0; k < KK; k++) {
        int off = soff[k], cnt = scnt[k];
        for (int p = tid; p < cnt; p += 512)
            g_rownode[off + p] = g_list[k][p];
    }
}

// ---------------- kernel 3: coarsen_adj = M adj M^T ----------------
__global__ __launch_bounds__(256) void k_coarsen(const float* __restrict__ adj) {
    __shared__ uint32_t msh[NN];
    int tid = threadIdx.x;
    for (int e = tid; e < NN; e += 256) msh[e] = g_mask[e];
    __syncthreads();

    int w = tid >> 5, lane = tid & 31;
    int i = blockIdx.x * 8 + w;

    float acc[KK];
    #pragma unroll
    for (int k = 0; k < KK; k++) acc[k] = 0.f;
    const float4* row = reinterpret_cast<const float4*>(adj + (size_t)i * NN);
    #pragma unroll 2
    for (int jt = 0; jt < NN / 128; jt++) {
        int j4 = jt * 32 + lane;
        float4 v = row[j4];
        int j = j4 * 4;
        uint32_t m0 = msh[j], m1 = msh[j + 1], m2 = msh[j + 2], m3 = msh[j + 3];
        #pragma unroll
        for (int bb = 0; bb < KK; bb++) {
            float s = 0.f;
            if (m0 & (1u << bb)) s += v.x;
            if (m1 & (1u << bb)) s += v.y;
            if (m2 & (1u << bb)) s += v.z;
            if (m3 & (1u << bb)) s += v.w;
            acc[bb] += s;
        }
    }
    uint32_t mi = g_mask[i];
    #pragma unroll
    for (int bb = 0; bb < KK; bb++) {
        float val = acc[bb];
        #pragma unroll
        for (int off = 16; off > 0; off >>= 1)
            val += __shfl_xor_sync(0xffffffffu, val, off);
        if (lane == 0) {
            uint32_t ma = mi;
            while (ma) {
                int a = __ffs(ma) - 1;
                ma &= ma - 1;
                atomicAdd(&g_coarsen[a * KK + bb], val);
            }
        }
    }
}

// ---------------- kernel 4: gather cluster-sorted X and A ----------------
// grid (KK, 16), 256 threads.
__global__ __launch_bounds__(256) void k_gather(const float* __restrict__ adj,
                                                const float* __restrict__ x) {
    int k = blockIdx.x;
    int by = blockIdx.y;
    int cnt = g_cnt[k];
    int off = g_off[k];
    int cp64 = (cnt + 63) & ~63;
    int c16 = (cnt + 15) & ~15;
    if (cp64 == 0) return;

    __shared__ int jl[NN];
    int tid = threadIdx.x;
    for (int j = tid; j < c16; j += 256) jl[j] = (j < cnt) ? g_list[k][j] : -1;
    __syncthreads();

    // X copy
    {
        int rsub = tid >> 6, c4 = (tid & 63) << 2;
        for (int pos = by * 4 + rsub; pos < cp64; pos += 64) {
            int gi = (pos < cnt) ? jl[pos] : -1;
            float4 v = make_float4(0.f, 0.f, 0.f, 0.f);
            if (gi >= 0) v = *reinterpret_cast<const float4*>(x + (size_t)gi * FF + c4);
            *reinterpret_cast<float4*>(g_xk + (size_t)(off + pos) * FF + c4) = v;
        }
    }
    // A gather: one row per block sweep, float4 stores (c16 is 16-aligned)
    for (int pos = by; pos < cp64; pos += 16) {
        int gi = (pos < cnt) ? jl[pos] : -1;
        float4* dst = reinterpret_cast<float4*>(g_ak + (size_t)(off + pos) * NN);
        if (gi >= 0) {
            const float* src = adj + (size_t)gi * NN;
            for (int j4 = tid; j4 < (c16 >> 2); j4 += 256) {
                int j = j4 << 2;
                int ga = jl[j], gb = jl[j + 1], gc = jl[j + 2], gd = jl[j + 3];
                float4 v;
                v.x = (ga >= 0) ? src[ga] : 0.f;
                v.y = (gb >= 0) ? src[gb] : 0.f;
                v.z = (gc >= 0) ? src[gc] : 0.f;
                v.w = (gd >= 0) ? src[gd] : 0.f;
                dst[j4] = v;
            }
        } else {
            float4 z = make_float4(0.f, 0.f, 0.f, 0.f);
            for (int j4 = tid; j4 < (c16 >> 2); j4 += 256) dst[j4] = z;
        }
    }
}

// ---------------- kernel 5: t = A_kk @ X_k + 2 X_k ----------------
// grid (TILES_MAX, 4), 256 threads. 64x64 tile, 4x4 per thread.
__global__ __launch_bounds__(256) void k_agg() {
    int tile = blockIdx.x, ct = blockIdx.y;
    int k = g_tilek[tile];
    if (k < 0) return;
    int cnt = g_cnt[k];
    int c16 = (cnt + 15) & ~15;
    int row0 = tile * 64;
    int offk = g_off[k];

    __shared__ float a_sh[16][65];   // [kk][r]
    __shared__ float x_sh[16][68];   // [kk][c]

    int tid = threadIdx.x;
    int tx = tid & 15, ty = tid >> 4;

    float acc[4][4];
    #pragma unroll
    for (int i = 0; i < 4; i++)
        #pragma unroll
        for (int j = 0; j < 4; j++) acc[i][j] = 0.f;

    int ar = tid >> 2, aq = (tid & 3) << 2;
    int xf = tid >> 4, xc = (tid & 15) << 2;

    for (int kb = 0; kb < c16; kb += 16) {
        __syncthreads();
        float4 av = *reinterpret_cast<const float4*>(g_ak + (size_t)(row0 + ar) * NN + kb + aq);
        a_sh[aq + 0][ar] = av.x; a_sh[aq + 1][ar] = av.y;
        a_sh[aq + 2][ar] = av.z; a_sh[aq + 3][ar] = av.w;
        *reinterpret_cast<float4*>(&x_sh[xf][xc]) =
            *reinterpret_cast<const float4*>(g_xk + (size_t)(offk + kb + xf) * FF + ct * 64 + xc);
        __syncthreads();
        #pragma unroll
        for (int kk = 0; kk < 16; kk++) {
            float a0 = a_sh[kk][ty * 4 + 0];
            float a1 = a_sh[kk][ty * 4 + 1];
            float a2 = a_sh[kk][ty * 4 + 2];
            float a3 = a_sh[kk][ty * 4 + 3];
            float4 wv = *reinterpret_cast<const float4*>(&x_sh[kk][tx * 4]);
            acc[0][0] += a0 * wv.x; acc[0][1] += a0 * wv.y; acc[0][2] += a0 * wv.z; acc[0][3] += a0 * wv.w;
            acc[1][0] += a1 * wv.x; acc[1][1] += a1 * wv.y; acc[1][2] += a1 * wv.z; acc[1][3] += a1 * wv.w;
            acc[2][0] += a2 * wv.x; acc[2][1] += a2 * wv.y; acc[2][2] += a2 * wv.z; acc[2][3] += a2 * wv.w;
            acc[3][0] += a3 * wv.x; acc[3][1] += a3 * wv.y; acc[3][2] += a3 * wv.z; acc[3][3] += a3 * wv.w;
        }
    }

    #pragma unroll
    for (int i = 0; i < 4; i++) {
        int row = row0 + ty * 4 + i;
        float4 xv = *reinterpret_cast<const float4*>(g_xk + (size_t)row * FF + ct * 64 + tx * 4);
        float4 o = make_float4(acc[i][0] + 2.f * xv.x, acc[i][1] + 2.f * xv.y,
                               acc[i][2] + 2.f * xv.z, acc[i][3] + 2.f * xv.w);
        *reinterpret_cast<float4*>(g_t + (size_t)row * FF + ct * 64 + tx * 4) = o;
    }
}

// ---------------- kernel 6: y = t @ W_k ----------------
// grid (TILES_MAX, 4), 256 threads. 64x64 tile, 4x4 per thread, K=256.
__global__ __launch_bounds__(256) void k_wgemm(const float* __restrict__ W) {
    int tile = blockIdx.x, ct = blockIdx.y;
    int k = g_tilek[tile];
    if (k < 0) return;
    int row0 = tile * 64;
    const float* Wk = W + (size_t)k * FF * OO;

    __shared__ float t_sh[16][65];   // [kk][r]
    __shared__ float w_sh[16][68];   // [kk][c]

    int tid = threadIdx.x;
    int tx = tid & 15, ty = tid >> 4;

    float acc[4][4];
    #pragma unroll
    for (int i = 0; i < 4; i++)
        #pragma unroll
        for (int j = 0; j < 4; j++) acc[i][j] = 0.f;

    int ar = tid >> 2, aq = (tid & 3) << 2;
    int wf = tid >> 4, wc = (tid & 15) << 2;

    for (int kb = 0; kb < FF; kb += 16) {
        __syncthreads();
        float4 tv = *reinterpret_cast<const float4*>(g_t + (size_t)(row0 + ar) * FF + kb + aq);
        t_sh[aq + 0][ar] = tv.x; t_sh[aq + 1][ar] = tv.y;
        t_sh[aq + 2][ar] = tv.z; t_sh[aq + 3][ar] = tv.w;
        *reinterpret_cast<float4*>(&w_sh[wf][wc]) =
            *reinterpret_cast<const float4*>(Wk + (size_t)(kb + wf) * OO + ct * 64 + wc);
        __syncthreads();
        #pragma unroll
        for (int kk = 0; kk < 16; kk++) {
            float a0 = t_sh[kk][ty * 4 + 0];
            float a1 = t_sh[kk][ty * 4 + 1];
            float a2 = t_sh[kk][ty * 4 + 2];
            float a3 = t_sh[kk][ty * 4 + 3];
            float4 wv = *reinterpret_cast<const float4*>(&w_sh[kk][tx * 4]);
            acc[0][0] += a0 * wv.x; acc[0][1] += a0 * wv.y; acc[0][2] += a0 * wv.z; acc[0][3] += a0 * wv.w;
            acc[1][0] += a1 * wv.x; acc[1][1] += a1 * wv.y; acc[1][2] += a1 * wv.z; acc[1][3] += a1 * wv.w;
            acc[2][0] += a2 * wv.x; acc[2][1] += a2 * wv.y; acc[2][2] += a2 * wv.z; acc[2][3] += a2 * wv.w;
            acc[3][0] += a3 * wv.x; acc[3][1] += a3 * wv.y; acc[3][2] += a3 * wv.z; acc[3][3] += a3 * wv.w;
        }
    }

    #pragma unroll
    for (int i = 0; i < 4; i++) {
        int row = row0 + ty * 4 + i;
        *reinterpret_cast<float4*>(g_y + (size_t)row * OO + ct * 64 + tx * 4) =
            make_float4(acc[i][0], acc[i][1], acc[i][2], acc[i][3]);
    }
}

// ---------------- kernel 7: L2 normalize rows + scatter into g_h ----------------
__global__ __launch_bounds__(256) void k_norm() {
    int w = threadIdx.x >> 5, lane = threadIdx.x & 31;
    int r = blockIdx.x * 8 + w;
    int gi = g_rownode[r];
    if (gi < 0) return;

    const float4* yr = reinterpret_cast<const float4*>(g_y + (size_t)r * OO);
    float4 a = yr[lane * 2], b = yr[lane * 2 + 1];
    float ss = a.x * a.x + a.y * a.y + a.z * a.z + a.w * a.w
             + b.x * b.x + b.y * b.y + b.z * b.z + b.w * b.w;
    #pragma unroll
    for (int off = 16; off > 0; off >>= 1)
        ss += __shfl_xor_sync(0xffffffffu, ss, off);
    float rn = 1.f / fmaxf(sqrtf(ss), 1e-12f);

    float* hb = g_h + (size_t)gi * OO + lane * 8;
    atomicAdd(hb + 0, a.x * rn); atomicAdd(hb + 1, a.y * rn);
    atomicAdd(hb + 2, a.z * rn); atomicAdd(hb + 3, a.w * rn);
    atomicAdd(hb + 4, b.x * rn); atomicAdd(hb + 5, b.y * rn);
    atomicAdd(hb + 6, b.z * rn); atomicAdd(hb + 7, b.w * rn);
}

// ---------------- kernel 8: BN column stats over relu(h) ----------------
__global__ __launch_bounds__(256) void k_stats() {
    int o = threadIdx.x;
    int rb = blockIdx.x * 32;
    float s = 0.f, ss = 0.f;
    #pragma unroll 8
    for (int r = 0; r < 32; r++) {
        float v = fmaxf(g_h[(size_t)(rb + r) * OO + o], 0.f);
        s += v;
        ss += v * v;
    }
    atomicAdd(&g_sum[o], s);
    atomicAdd(&g_sumsq[o], ss);
}

// ---------------- kernel 9: final output ----------------
__global__ __launch_bounds__(256) void k_final(float* __restrict__ out) {
    int k = blockIdx.x, o = threadIdx.x;
    int cnt = g_cnt[k];
    float S = 0.f;
    for (int p = 0; p < cnt; p++) {
        int gi = g_list[k][p];
        S += fmaxf(g_h[(size_t)gi * OO + o], 0.f);
    }
    float mean = g_sum[o] * (1.f / NN);
    float var = g_sumsq[o] * (1.f / NN) - mean * mean;
    float rstd = rsqrtf(var + 1e-5f);
    out[k * OO + o] = (S - (float)cnt * mean) * rstd;
    if (o < KK) out[KK * OO + k * KK + o] = g_coarsen[k * KK + o];
}

// ---------------- launch ----------------
extern "C" void kernel_launch(void* const* d_in, const int* in_sizes, int n_in,
                              void* d_out, int out_size) {
    const float* x   = (const float*)d_in[0];
    const float* adj = (const float*)d_in[1];
    const float* wp  = (const float*)d_in[2];
    const float* bp  = (const float*)d_in[3];
    const float* W   = (const float*)d_in[4];
    float* out = (float*)d_out;

    k_partition<<<256, 256>>>(x, wp, bp);
    k_lists<<<1, 512>>>();
    k_coarsen<<<256, 256>>>(adj);
    k_gather<<<dim3(KK, 16), 256>>>(adj, x);
    k_agg<<<dim3(TILES_MAX, 4), 256>>>();
    k_wgemm<<<dim3(TILES_MAX, 4), 256>>>(W);
    k_norm<<<ROWS_MAX / 8, 256>>>();
    k_stats<<<64, 256>>>();
    k_final<<<KK, 256>>>(out);
}

// round 5
// speedup vs baseline: 1.5954x; 1.1406x over previous
#include <cuda_runtime.h>
#include <cstdint>

#define NN 2048
#define KK 16
#define FF 256
#define OO 256
#define ROWS_MAX 4096
#define TILES_MAX 64

// ---------------- scratch (device globals; no allocation) ----------------
__device__ uint32_t g_mask[NN];
__device__ int      g_cnt[KK];
__device__ int      g_off[KK];
__device__ int      g_list[KK][NN];
__device__ int      g_tilek[TILES_MAX];
__device__ int      g_rownode[ROWS_MAX];
__device__ float    g_xk[ROWS_MAX * FF];          // cluster-sorted x (zero padded)
__device__ float    g_ak[(size_t)ROWS_MAX * NN];  // cluster-sorted A_kk rows (zero padded)
__device__ float    g_t[ROWS_MAX * FF];
__device__ float    g_y[ROWS_MAX * OO];
__device__ float    g_y2[ROWS_MAX * OO];          // split-K partial
__device__ float    g_h[NN * OO];
__device__ float    g_coarsen[KK * KK];
__device__ float    g_sum[OO];
__device__ float    g_sumsq[OO];
__device__ float    g_S[KK * OO];

// ---------------- kernel 1: partition + zero accumulators ----------------
__global__ __launch_bounds__(256) void k_partition(const float* __restrict__ x,
                                                   const float* __restrict__ wp,
                                                   const float* __restrict__ bp) {
    __shared__ float wsh[KK][FF];
    int tid = threadIdx.x;
    int b = blockIdx.x;

    for (int e = tid; e < FF * KK; e += 256) {
        int f = e / KK, k = e % KK;
        wsh[k][f] = wp[e];
    }
    #pragma unroll
    for (int q = 0; q < 8; q++)
        g_h[b * 2048 + q * 256 + tid] = 0.f;
    if (b == 0) {
        if (tid < KK * KK) g_coarsen[tid] = 0.f;
        g_sum[tid] = 0.f;
        g_sumsq[tid] = 0.f;
        #pragma unroll
        for (int e = 0; e < KK; e++) g_S[e * 256 + tid] = 0.f;
    }
    __syncthreads();

    int w = tid >> 5, lane = tid & 31;
    int i = b * 8 + w;

    float acc[KK];
    #pragma unroll
    for (int k = 0; k < KK; k++) acc[k] = 0.f;

    #pragma unroll
    for (int it = 0; it < 8; it++) {
        int f = it * 32 + lane;
        float xv = x[i * FF + f];
        #pragma unroll
        for (int k = 0; k < KK; k++) acc[k] += xv * wsh[k][f];
    }
    #pragma unroll
    for (int k = 0; k < KK; k++) {
        #pragma unroll
        for (int off = 16; off > 0; off >>= 1)
            acc[k] += __shfl_xor_sync(0xffffffffu, acc[k], off);
    }
    float mx = -1.f;
    #pragma unroll
    for (int k = 0; k < KK; k++) {
        float r = fmaxf(acc[k] + bp[k], 0.f);
        acc[k] = r;
        mx = fmaxf(mx, r);
    }
    uint32_t msk = 0;
    #pragma unroll
    for (int k = 0; k < KK; k++)
        if (acc[k] == mx) msk |= (1u << k);
    if (lane == 0) g_mask[i] = msk;
}

// ---------------- kernel 2: lists + offsets + tile map + rownode ----------------
__global__ __launch_bounds__(512) void k_lists() {
    int tid = threadIdx.x;
    int w = tid >> 5, lane = tid & 31;
    __shared__ int scnt[KK];
    __shared__ int soff[KK + 1];

    if (w < KK) {
        int cnt = 0;
        for (int base = 0; base < NN; base += 32) {
            uint32_t m = g_mask[base + lane];
            int pred = (m >> w) & 1u;
            unsigned bal = __ballot_sync(0xffffffffu, pred);
            if (pred) {
                int pos = cnt + __popc(bal & ((1u << lane) - 1u));
                g_list[w][pos] = base + lane;
            }
            cnt += __popc(bal);
        }
        if (lane == 0) { g_cnt[w] = cnt; scnt[w] = cnt; }
    }
    __syncthreads();

    if (tid == 0) {
        int o = 0;
        for (int k = 0; k < KK; k++) {
            soff[k] = o;
            g_off[k] = o;
            o += (scnt[k] + 63) & ~63;
        }
        soff[KK] = o;
        for (int t = 0; t < TILES_MAX; t++) g_tilek[t] = -1;
        for (int k = 0; k < KK; k++) {
            int t0 = soff[k] >> 6;
            int t1 = (soff[k] + ((scnt[k] + 63) & ~63)) >> 6;
            for (int t = t0; t < t1; t++) g_tilek[t] = k;
        }
    }
    __syncthreads();

    for (int r = tid; r < ROWS_MAX; r += 512) g_rownode[r] = -1;
    __syncthreads();
    for (int k = 0; k < KK; k++) {
        int off = soff[k], cnt = scnt[k];
        for (int p = tid; p < cnt; p += 512)
            g_rownode[off + p] = g_list[k][p];
    }
}

// ---------------- kernel 3: coarsen_adj = M adj M^T ----------------
__global__ __launch_bounds__(256) void k_coarsen(const float* __restrict__ adj) {
    __shared__ uint32_t msh[NN];
    int tid = threadIdx.x;
    for (int e = tid; e < NN; e += 256) msh[e] = g_mask[e];
    __syncthreads();

    int w = tid >> 5, lane = tid & 31;
    int i = blockIdx.x * 8 + w;

    float acc[KK];
    #pragma unroll
    for (int k = 0; k < KK; k++) acc[k] = 0.f;
    const float4* row = reinterpret_cast<const float4*>(adj + (size_t)i * NN);
    #pragma unroll 2
    for (int jt = 0; jt < NN / 128; jt++) {
        int j4 = jt * 32 + lane;
        float4 v = row[j4];
        int j = j4 * 4;
        uint32_t m0 = msh[j], m1 = msh[j + 1], m2 = msh[j + 2], m3 = msh[j + 3];
        #pragma unroll
        for (int bb = 0; bb < KK; bb++) {
            float s = 0.f;
            if (m0 & (1u << bb)) s += v.x;
            if (m1 & (1u << bb)) s += v.y;
            if (m2 & (1u << bb)) s += v.z;
            if (m3 & (1u << bb)) s += v.w;
            acc[bb] += s;
        }
    }
    uint32_t mi = g_mask[i];
    #pragma unroll
    for (int bb = 0; bb < KK; bb++) {
        float val = acc[bb];
        #pragma unroll
        for (int off = 16; off > 0; off >>= 1)
            val += __shfl_xor_sync(0xffffffffu, val, off);
        if (lane == 0) {
            uint32_t ma = mi;
            while (ma) {
                int a = __ffs(ma) - 1;
                ma &= ma - 1;
                atomicAdd(&g_coarsen[a * KK + bb], val);
            }
        }
    }
}

// ---------------- kernel 4: gather cluster-sorted X and A ----------------
// grid (KK, 64), 256 threads.
__global__ __launch_bounds__(256) void k_gather(const float* __restrict__ adj,
                                                const float* __restrict__ x) {
    int k = blockIdx.x;
    int by = blockIdx.y;
    int cnt = g_cnt[k];
    int off = g_off[k];
    int cp64 = (cnt + 63) & ~63;
    int c16 = (cnt + 15) & ~15;
    if (cp64 == 0) return;

    __shared__ int jl[NN];
    int tid = threadIdx.x;
    for (int j = tid; j < c16; j += 256) jl[j] = (j < cnt) ? g_list[k][j] : -1;
    __syncthreads();

    // X copy: spread over all 64 blocks
    {
        int rsub = tid >> 6, c4 = (tid & 63) << 2;
        for (int pos = by * 4 + rsub; pos < cp64; pos += 256) {
            int gi = (pos < cnt) ? jl[pos] : -1;
            float4 v = make_float4(0.f, 0.f, 0.f, 0.f);
            if (gi >= 0) v = *reinterpret_cast<const float4*>(x + (size_t)gi * FF + c4);
            *reinterpret_cast<float4*>(g_xk + (size_t)(off + pos) * FF + c4) = v;
        }
    }
    // A gather: one row per block sweep, float4 stores
    for (int pos = by; pos < cp64; pos += 64) {
        int gi = (pos < cnt) ? jl[pos] : -1;
        float4* dst = reinterpret_cast<float4*>(g_ak + (size_t)(off + pos) * NN);
        if (gi >= 0) {
            const float* src = adj + (size_t)gi * NN;
            for (int j4 = tid; j4 < (c16 >> 2); j4 += 256) {
                int j = j4 << 2;
                int ga = jl[j], gb = jl[j + 1], gc = jl[j + 2], gd = jl[j + 3];
                float4 v;
                v.x = (ga >= 0) ? src[ga] : 0.f;
                v.y = (gb >= 0) ? src[gb] : 0.f;
                v.z = (gc >= 0) ? src[gc] : 0.f;
                v.w = (gd >= 0) ? src[gd] : 0.f;
                dst[j4] = v;
            }
        } else {
            float4 z = make_float4(0.f, 0.f, 0.f, 0.f);
            for (int j4 = tid; j4 < (c16 >> 2); j4 += 256) dst[j4] = z;
        }
    }
}

// ---------------- kernel 5: t = A_kk @ X_k + 2 X_k ----------------
// grid (TILES_MAX, 4), 256 threads. 64x64 tile, 4x4/thread, kb=32, reg prefetch.
__global__ __launch_bounds__(256) void k_agg() {
    int tile = blockIdx.x, ct = blockIdx.y;
    int k = g_tilek[tile];
    if (k < 0) return;
    int cnt = g_cnt[k];
    int c32 = (cnt + 31) & ~31;
    int row0 = tile * 64;
    int offk = g_off[k];

    __shared__ float a_sh[32][65];   // [kk][r]
    __shared__ float x_sh[32][68];   // [kk][c]

    int tid = threadIdx.x;
    int tx = tid & 15, ty = tid >> 4;
    int ar = tid >> 2, aq = (tid & 3) << 2;
    int xf = tid >> 4, xc = (tid & 15) << 2;

    const float* abase = g_ak + (size_t)(row0 + ar) * NN;
    float4 pa0, pa1, px0, px1;
    // prefetch chunk 0
    pa0 = *reinterpret_cast<const float4*>(abase + aq);
    pa1 = *reinterpret_cast<const float4*>(abase + 16 + aq);
    px0 = *reinterpret_cast<const float4*>(g_xk + (size_t)(offk + xf) * FF + ct * 64 + xc);
    px1 = *reinterpret_cast<const float4*>(g_xk + (size_t)(offk + 16 + xf) * FF + ct * 64 + xc);

    float acc[4][4];
    #pragma unroll
    for (int i = 0; i < 4; i++)
        #pragma unroll
        for (int j = 0; j < 4; j++) acc[i][j] = 0.f;

    for (int kb = 0; kb < c32; kb += 32) {
        a_sh[aq + 0][ar] = pa0.x; a_sh[aq + 1][ar] = pa0.y;
        a_sh[aq + 2][ar] = pa0.z; a_sh[aq + 3][ar] = pa0.w;
        a_sh[aq + 16][ar] = pa1.x; a_sh[aq + 17][ar] = pa1.y;
        a_sh[aq + 18][ar] = pa1.z; a_sh[aq + 19][ar] = pa1.w;
        *reinterpret_cast<float4*>(&x_sh[xf][xc]) = px0;
        *reinterpret_cast<float4*>(&x_sh[xf + 16][xc]) = px1;
        __syncthreads();
        int kn = kb + 32;
        if (kn < c32) {
            pa0 = *reinterpret_cast<const float4*>(abase + kn + aq);
            pa1 = *reinterpret_cast<const float4*>(abase + kn + 16 + aq);
            px0 = *reinterpret_cast<const float4*>(g_xk + (size_t)(offk + kn + xf) * FF + ct * 64 + xc);
            px1 = *reinterpret_cast<const float4*>(g_xk + (size_t)(offk + kn + 16 + xf) * FF + ct * 64 + xc);
        }
        #pragma unroll
        for (int kk = 0; kk < 32; kk++) {
            float a0 = a_sh[kk][ty * 4 + 0];
            float a1 = a_sh[kk][ty * 4 + 1];
            float a2 = a_sh[kk][ty * 4 + 2];
            float a3 = a_sh[kk][ty * 4 + 3];
            float4 wv = *reinterpret_cast<const float4*>(&x_sh[kk][tx * 4]);
            acc[0][0] += a0 * wv.x; acc[0][1] += a0 * wv.y; acc[0][2] += a0 * wv.z; acc[0][3] += a0 * wv.w;
            acc[1][0] += a1 * wv.x; acc[1][1] += a1 * wv.y; acc[1][2] += a1 * wv.z; acc[1][3] += a1 * wv.w;
            acc[2][0] += a2 * wv.x; acc[2][1] += a2 * wv.y; acc[2][2] += a2 * wv.z; acc[2][3] += a2 * wv.w;
            acc[3][0] += a3 * wv.x; acc[3][1] += a3 * wv.y; acc[3][2] += a3 * wv.z; acc[3][3] += a3 * wv.w;
        }
        __syncthreads();
    }

    #pragma unroll
    for (int i = 0; i < 4; i++) {
        int row = row0 + ty * 4 + i;
        float4 xv = *reinterpret_cast<const float4*>(g_xk + (size_t)row * FF + ct * 64 + tx * 4);
        float4 o = make_float4(acc[i][0] + 2.f * xv.x, acc[i][1] + 2.f * xv.y,
                               acc[i][2] + 2.f * xv.z, acc[i][3] + 2.f * xv.w);
        *reinterpret_cast<float4*>(g_t + (size_t)row * FF + ct * 64 + tx * 4) = o;
    }
}

// ---------------- kernel 6: y = t @ W_k (split-K = 2) ----------------
// grid (TILES_MAX, 4, 2), 256 threads. 64x64 tile, 4x4/thread, kb=32, reg prefetch.
__global__ __launch_bounds__(256) void k_wgemm(const float* __restrict__ W) {
    int tile = blockIdx.x, ct = blockIdx.y, z = blockIdx.z;
    int k = g_tilek[tile];
    if (k < 0) return;
    int row0 = tile * 64;
    const float* Wk = W + (size_t)k * FF * OO;
    int kbase = z * 128;

    __shared__ float t_sh[32][65];   // [kk][r]
    __shared__ float w_sh[32][68];   // [kk][c]

    int tid = threadIdx.x;
    int tx = tid & 15, ty = tid >> 4;
    int ar = tid >> 2, aq = (tid & 3) << 2;
    int wf = tid >> 4, wc = (tid & 15) << 2;

    const float* tbase = g_t + (size_t)(row0 + ar) * FF + kbase;
    float4 pt0, pt1, pw0, pw1;
    pt0 = *reinterpret_cast<const float4*>(tbase + aq);
    pt1 = *reinterpret_cast<const float4*>(tbase + 16 + aq);
    pw0 = *reinterpret_cast<const float4*>(Wk + (size_t)(kbase + wf) * OO + ct * 64 + wc);
    pw1 = *reinterpret_cast<const float4*>(Wk + (size_t)(kbase + 16 + wf) * OO + ct * 64 + wc);

    float acc[4][4];
    #pragma unroll
    for (int i = 0; i < 4; i++)
        #pragma unroll
        for (int j = 0; j < 4; j++) acc[i][j] = 0.f;

    #pragma unroll 1
    for (int kb = 0; kb < 128; kb += 32) {
        t_sh[aq + 0][ar] = pt0.x; t_sh[aq + 1][ar] = pt0.y;
        t_sh[aq + 2][ar] = pt0.z; t_sh[aq + 3][ar] = pt0.w;
        t_sh[aq + 16][ar] = pt1.x; t_sh[aq + 17][ar] = pt1.y;
        t_sh[aq + 18][ar] = pt1.z; t_sh[aq + 19][ar] = pt1.w;
        *reinterpret_cast<float4*>(&w_sh[wf][wc]) = pw0;
        *reinterpret_cast<float4*>(&w_sh[wf + 16][wc]) = pw1;
        __syncthreads();
        int kn = kb + 32;
        if (kn < 128) {
            pt0 = *reinterpret_cast<const float4*>(tbase + kn + aq);
            pt1 = *reinterpret_cast<const float4*>(tbase + kn + 16 + aq);
            pw0 = *reinterpret_cast<const float4*>(Wk + (size_t)(kbase + kn + wf) * OO + ct * 64 + wc);
            pw1 = *reinterpret_cast<const float4*>(Wk + (size_t)(kbase + kn + 16 + wf) * OO + ct * 64 + wc);
        }
        #pragma unroll
        for (int kk = 0; kk < 32; kk++) {
            float a0 = t_sh[kk][ty * 4 + 0];
            float a1 = t_sh[kk][ty * 4 + 1];
            float a2 = t_sh[kk][ty * 4 + 2];
            float a3 = t_sh[kk][ty * 4 + 3];
            float4 wv = *reinterpret_cast<const float4*>(&w_sh[kk][tx * 4]);
            acc[0][0] += a0 * wv.x; acc[0][1] += a0 * wv.y; acc[0][2] += a0 * wv.z; acc[0][3] += a0 * wv.w;
            acc[1][0] += a1 * wv.x; acc[1][1] += a1 * wv.y; acc[1][2] += a1 * wv.z; acc[1][3] += a1 * wv.w;
            acc[2][0] += a2 * wv.x; acc[2][1] += a2 * wv.y; acc[2][2] += a2 * wv.z; acc[2][3] += a2 * wv.w;
            acc[3][0] += a3 * wv.x; acc[3][1] += a3 * wv.y; acc[3][2] += a3 * wv.z; acc[3][3] += a3 * wv.w;
        }
        __syncthreads();
    }

    float* yb = z ? g_y2 : g_y;
    #pragma unroll
    for (int i = 0; i < 4; i++) {
        int row = row0 + ty * 4 + i;
        *reinterpret_cast<float4*>(yb + (size_t)row * OO + ct * 64 + tx * 4) =
            make_float4(acc[i][0], acc[i][1], acc[i][2], acc[i][3]);
    }
}

// ---------------- kernel 7: L2 normalize rows + scatter into g_h ----------------
__global__ __launch_bounds__(256) void k_norm() {
    int w = threadIdx.x >> 5, lane = threadIdx.x & 31;
    int r = blockIdx.x * 8 + w;
    int gi = g_rownode[r];
    if (gi < 0) return;

    const float4* yr  = reinterpret_cast<const float4*>(g_y  + (size_t)r * OO);
    const float4* yr2 = reinterpret_cast<const float4*>(g_y2 + (size_t)r * OO);
    float4 a = yr[lane * 2], b = yr[lane * 2 + 1];
    float4 a2 = yr2[lane * 2], b2 = yr2[lane * 2 + 1];
    a.x += a2.x; a.y += a2.y; a.z += a2.z; a.w += a2.w;
    b.x += b2.x; b.y += b2.y; b.z += b2.z; b.w += b2.w;
    float ss = a.x * a.x + a.y * a.y + a.z * a.z + a.w * a.w
             + b.x * b.x + b.y * b.y + b.z * b.z + b.w * b.w;
    #pragma unroll
    for (int off = 16; off > 0; off >>= 1)
        ss += __shfl_xor_sync(0xffffffffu, ss, off);
    float rn = 1.f / fmaxf(sqrtf(ss), 1e-12f);

    float* hb = g_h + (size_t)gi * OO + lane * 8;
    atomicAdd(hb + 0, a.x * rn); atomicAdd(hb + 1, a.y * rn);
    atomicAdd(hb + 2, a.z * rn); atomicAdd(hb + 3, a.w * rn);
    atomicAdd(hb + 4, b.x * rn); atomicAdd(hb + 5, b.y * rn);
    atomicAdd(hb + 6, b.z * rn); atomicAdd(hb + 7, b.w * rn);
}

// ---------------- kernel 8: BN column stats over relu(h) ----------------
__global__ __launch_bounds__(256) void k_stats() {
    int o = threadIdx.x;
    int rb = blockIdx.x * 32;
    float s = 0.f, ss = 0.f;
    #pragma unroll 8
    for (int r = 0; r < 32; r++) {
        float v = fmaxf(g_h[(size_t)(rb + r) * OO + o], 0.f);
        s += v;
        ss += v * v;
    }
    atomicAdd(&g_sum[o], s);
    atomicAdd(&g_sumsq[o], ss);
}

// ---------------- kernel 9: per-cluster column partial sums ----------------
__global__ __launch_bounds__(256) void k_fsum() {
    int k = blockIdx.x, q = blockIdx.y, o = threadIdx.x;
    int cnt = g_cnt[k];
    float S = 0.f;
    for (int p = q; p < cnt; p += 8) {
        int gi = g_list[k][p];
        S += fmaxf(g_h[(size_t)gi * OO + o], 0.f);
    }
    atomicAdd(&g_S[k * OO + o], S);
}

// ---------------- kernel 10: final output ----------------
__global__ __launch_bounds__(256) void k_final(float* __restrict__ out) {
    int k = blockIdx.x, o = threadIdx.x;
    float mean = g_sum[o] * (1.f / NN);
    float var = g_sumsq[o] * (1.f / NN) - mean * mean;
    float rstd = rsqrtf(var + 1e-5f);
    out[k * OO + o] = (g_S[k * OO + o] - (float)g_cnt[k] * mean) * rstd;
    if (o < KK) out[KK * OO + k * KK + o] = g_coarsen[k * KK + o];
}

// ---------------- launch ----------------
extern "C" void kernel_launch(void* const* d_in, const int* in_sizes, int n_in,
                              void* d_out, int out_size) {
    const float* x   = (const float*)d_in[0];
    const float* adj = (const float*)d_in[1];
    const float* wp  = (const float*)d_in[2];
    const float* bp  = (const float*)d_in[3];
    const float* W   = (const float*)d_in[4];
    float* out = (float*)d_out;

    k_partition<<<256, 256>>>(x, wp, bp);
    k_lists<<<1, 512>>>();
    k_coarsen<<<256, 256>>>(adj);
    k_gather<<<dim3(KK, 64), 256>>>(adj, x);
    k_agg<<<dim3(TILES_MAX, 4), 256>>>();
    k_wgemm<<<dim3(TILES_MAX, 4, 2), 256>>>(W);
    k_norm<<<ROWS_MAX / 8, 256>>>();
    k_stats<<<64, 256>>>();
    k_fsum<<<dim3(KK, 8), 256>>>();
    k_final<<<KK, 256>>>(out);
}